// round 14
// baseline (speedup 1.0000x reference)
#include <cuda_runtime.h>
#include <cuda_fp16.h>
#include <math.h>
#include <stdint.h>

#define CT   4096
#define CHID 2560
#define CH   8
#define CKH  4
#define CD   256
#define CQD  2048   // H*D
#define CKD  1024   // KH*D
#define CWIN 1024
#define LOG2E 1.4426950408889634f
#define QSCALE (0.0625f * LOG2E)

// ---------------- scratch (static device globals) ----------------
__device__ float g_Q[CT * CQD];          // f32 Q proj (pre-norm)
__device__ float g_K[CT * CKD];          // f32 K proj (pre-norm)
__device__ float g_invf[128];

__device__ __half g_xs[CT * CHID];                  // x fp16
__device__ __half g_Wqkv[(CQD + 2 * CKD) * CHID];   // [4096, 2560] concat [N,K]
__device__ __half g_Wot[CHID * CQD];                // Wo^T [2560, 2048]

__device__ __half g_Qs[CT * CQD];        // flash operands fp16
__device__ __half g_Ks[CT * CKD];
__device__ __half g_Vs[CT * CKD];
__device__ __half g_AOs[CT * CQD];       // attention output fp16

extern __shared__ char dyn_smem[];

// ---------------- PTX helpers (compute_103-safe) ----------------
__device__ __forceinline__ uint32_t smem_u32(const void* p) {
    uint32_t a;
    asm("{ .reg .u64 t; cvta.to.shared.u64 t, %1; cvt.u32.u64 %0, t; }"
        : "=r"(a) : "l"(p));
    return a;
}
__device__ __forceinline__ void cp_async16(uint32_t s, const void* g) {
    asm volatile("cp.async.cg.shared.global [%0], [%1], 16;" :: "r"(s), "l"(g));
}
#define CP_COMMIT()  asm volatile("cp.async.commit_group;" ::: "memory")
#define CP_WAIT(n)   asm volatile("cp.async.wait_group %0;" :: "n"(n) : "memory")

#define LDSM_X4(r0, r1, r2, r3, addr) \
    asm volatile("ldmatrix.sync.aligned.m8n8.x4.shared.b16 {%0,%1,%2,%3}, [%4];" \
                 : "=r"(r0), "=r"(r1), "=r"(r2), "=r"(r3) : "r"(addr))
#define LDSM_X4_T(r0, r1, r2, r3, addr) \
    asm volatile("ldmatrix.sync.aligned.m8n8.x4.trans.shared.b16 {%0,%1,%2,%3}, [%4];" \
                 : "=r"(r0), "=r"(r1), "=r"(r2), "=r"(r3) : "r"(addr))

__device__ __forceinline__ void mma16816(float* d, const uint32_t* a,
                                         const uint32_t* b) {
    asm volatile(
        "mma.sync.aligned.m16n8k16.row.col.f32.f16.f16.f32 "
        "{%0,%1,%2,%3}, {%4,%5,%6,%7}, {%8,%9}, {%0,%1,%2,%3};"
        : "+f"(d[0]), "+f"(d[1]), "+f"(d[2]), "+f"(d[3])
        : "r"(a[0]), "r"(a[1]), "r"(a[2]), "r"(a[3]), "r"(b[0]), "r"(b[1]));
}
__device__ __forceinline__ float fast_exp2(float x) {
    float y;
    asm("ex2.approx.ftz.f32 %0, %1;" : "=f"(y) : "f"(x));
    return y;
}
__device__ __forceinline__ uint32_t packh2(float a, float b) {
    __half2 t = __floats2half2_rn(a, b);
    return *(uint32_t*)&t;
}

// ---------------- small prep kernels ----------------
__global__ void init_invf_kernel() {
    int d = threadIdx.x;
    if (d < 128) g_invf[d] = (float)pow(10000.0, -((double)d) / 128.0);
}

__global__ __launch_bounds__(256) void convert_f16_kernel(
    const float* __restrict__ x, __half* __restrict__ y, int n)
{
    int i = blockIdx.x * 256 + threadIdx.x;
    int stride = gridDim.x * 256;
    for (; i < n; i += stride) y[i] = __float2half_rn(x[i]);
}

// All weight transposes in ONE launch (z selects matrix). W[K,N] -> T[N,K] fp16.
__global__ __launch_bounds__(256) void transpose_all_kernel(
    const float* __restrict__ Wq, const float* __restrict__ Wk,
    const float* __restrict__ Wv, const float* __restrict__ Wo,
    __half* __restrict__ Wqkv, __half* __restrict__ Wot)
{
    const float* W;
    __half* Th;
    int K, N;
    switch (blockIdx.z) {
        case 0: W = Wq; Th = Wqkv;                              K = CHID; N = CQD; break;
        case 1: W = Wk; Th = Wqkv + (size_t)CQD * CHID;         K = CHID; N = CKD; break;
        case 2: W = Wv; Th = Wqkv + (size_t)(CQD + CKD) * CHID; K = CHID; N = CKD; break;
        default: W = Wo; Th = Wot;                              K = CQD;  N = CHID; break;
    }
    int n0 = blockIdx.x * 32, k0 = blockIdx.y * 32;
    if (n0 >= N || k0 >= K) return;

    __shared__ float t[32][33];
    int tx = threadIdx.x & 31, ty = threadIdx.x >> 5;
    #pragma unroll
    for (int r = 0; r < 4; r++)
        t[ty + 8 * r][tx] = W[(size_t)(k0 + ty + 8 * r) * N + n0 + tx];
    __syncthreads();
    #pragma unroll
    for (int r = 0; r < 4; r++)
        Th[(size_t)(n0 + ty + 8 * r) * K + k0 + tx] =
            __float2half_rn(t[tx][ty + 8 * r]);
}

// ---------------------------------------------------------------------------
// HMMA fp16 GEMM core v2: 128x256 CTA tile, 8 warps as 2x4 (64x64 warp tile),
// BK=64, 3-stage cp.async, ONE syncthreads per chunk.
// LDS/MMA balanced: 8 ldsm.x4 feed 32 MMAs per ks (1.0 cyc/MMA both pipes).
// ---------------------------------------------------------------------------
#define GSTG 49152                     // A 16KB + B 32KB
#define GEMM_SMEM (3 * GSTG)           // 144 KB

__device__ __forceinline__ void gemm_issue(
    uint32_t st, int tid, size_t aBase, size_t bBase, int k0, int K,
    const __half* __restrict__ A, const __half* __restrict__ B)
{
    #pragma unroll
    for (int it = 0; it < 4; it++) {           // A: 128 rows x 8 c16
        int id  = tid + it * 256;
        int row = id >> 3;
        int c16 = id & 7;
        uint32_t sw = (uint32_t)(row * 128) + ((uint32_t)(c16 ^ (row & 7)) << 4);
        cp_async16(st + sw, A + aBase + (size_t)row * K + k0 + c16 * 8);
    }
    #pragma unroll
    for (int it = 0; it < 8; it++) {           // B: 256 rows x 8 c16
        int id  = tid + it * 256;
        int row = id >> 3;
        int c16 = id & 7;
        uint32_t sw = (uint32_t)(row * 128) + ((uint32_t)(c16 ^ (row & 7)) << 4);
        cp_async16(st + 16384 + sw, B + bBase + (size_t)row * K + k0 + c16 * 8);
    }
    CP_COMMIT();
}

__device__ __forceinline__ void gemm_core(
    uint32_t smb, int tid, int wid, int lane,
    size_t aBase, size_t bBase, int K,
    const __half* __restrict__ A, const __half* __restrict__ B,
    float acc[4][8][4])
{
    const int warp_m = wid >> 2;       // 0..1 -> 64 rows
    const int warp_n = wid & 3;        // 0..3 -> 64 cols
    const int NC = K >> 6;
    const int row_in = lane & 15;
    const int hi     = lane >> 4;
    const uint32_t swkey = (uint32_t)(row_in & 7);

    gemm_issue(smb, tid, aBase, bBase, 0, K, A, B);
    if (NC > 1) gemm_issue(smb + GSTG, tid, aBase, bBase, 64, K, A, B);

    for (int c = 0; c < NC; c++) {
        CP_WAIT(1);
        __syncthreads();
        if (c + 2 < NC)
            gemm_issue(smb + ((c + 2) % 3) * GSTG, tid, aBase, bBase,
                       (c + 2) << 6, K, A, B);
        const uint32_t sA = smb + (c % 3) * GSTG;
        const uint32_t sB = sA + 16384;

        #pragma unroll
        for (int ks = 0; ks < 4; ks++) {
            const uint32_t csw = ((uint32_t)(ks * 2 + hi) ^ swkey) << 4;
            uint32_t ah[4][4];
            #pragma unroll
            for (int mt = 0; mt < 4; mt++) {
                uint32_t off = (uint32_t)(warp_m * 64 + mt * 16 + row_in) * 128 + csw;
                LDSM_X4(ah[mt][0], ah[mt][1], ah[mt][2], ah[mt][3], sA + off);
            }
            uint32_t bf[8][2];
            #pragma unroll
            for (int p = 0; p < 4; p++) {
                uint32_t off = (uint32_t)(warp_n * 64 + p * 16 + row_in) * 128 + csw;
                uint32_t r0, r1, r2, r3;
                LDSM_X4(r0, r1, r2, r3, sB + off);
                bf[2 * p][0] = r0; bf[2 * p + 1][0] = r1;
                bf[2 * p][1] = r2; bf[2 * p + 1][1] = r3;
            }
            #pragma unroll
            for (int mt = 0; mt < 4; mt++)
                #pragma unroll
                for (int nt = 0; nt < 8; nt++)
                    mma16816(acc[mt][nt], ah[mt], bf[nt]);
        }
    }
}

// Fused QKV projection: N = 4096 concat (Q 2048 f32 | K 1024 f32 | V 1024 fp16)
// N-blocks of 256 lie entirely within one section.
__global__ __launch_bounds__(256, 1) void gemm_qkv_kernel(
    const __half* __restrict__ xs, const __half* __restrict__ Wqkv,
    float* __restrict__ Qf, float* __restrict__ Kf, __half* __restrict__ Vh)
{
    const uint32_t smb = smem_u32(dyn_smem);
    const int tid = threadIdx.x, wid = tid >> 5, lane = tid & 31;
    const int m0 = blockIdx.y * 128, n0 = blockIdx.x * 256;

    float acc[4][8][4];
    #pragma unroll
    for (int mt = 0; mt < 4; mt++)
        #pragma unroll
        for (int nt = 0; nt < 8; nt++)
            #pragma unroll
            for (int r = 0; r < 4; r++) acc[mt][nt][r] = 0.0f;

    gemm_core(smb, tid, wid, lane, (size_t)m0 * CHID, (size_t)n0 * CHID,
              CHID, xs, Wqkv, acc);

    float* Cf = nullptr; __half* Chh = nullptr;
    int ld, cb;
    if (n0 < CQD)            { Cf = Qf; ld = CQD; cb = n0; }
    else if (n0 < CQD + CKD) { Cf = Kf; ld = CKD; cb = n0 - CQD; }
    else                     { Chh = Vh; ld = CKD; cb = n0 - CQD - CKD; }

    const int warp_m = wid >> 2, warp_n = wid & 3;
    #pragma unroll
    for (int mt = 0; mt < 4; mt++) {
        int row = m0 + warp_m * 64 + mt * 16 + (lane >> 2);
        #pragma unroll
        for (int nt = 0; nt < 8; nt++) {
            int col = cb + warp_n * 64 + nt * 8 + (lane & 3) * 2;
            if (Chh) {
                *(__half2*)&Chh[(size_t)row * ld + col] =
                    __floats2half2_rn(acc[mt][nt][0], acc[mt][nt][1]);
                *(__half2*)&Chh[(size_t)(row + 8) * ld + col] =
                    __floats2half2_rn(acc[mt][nt][2], acc[mt][nt][3]);
            } else {
                *(float2*)&Cf[(size_t)row * ld + col] =
                    make_float2(acc[mt][nt][0], acc[mt][nt][1]);
                *(float2*)&Cf[(size_t)(row + 8) * ld + col] =
                    make_float2(acc[mt][nt][2], acc[mt][nt][3]);
            }
        }
    }
}

// Output projection: out[T, HID] = AO[T, QD] @ Wot[HID, QD]^T, f32 out
__global__ __launch_bounds__(256, 1) void gemm_o_kernel(
    const __half* __restrict__ AOs, const __half* __restrict__ Wot,
    float* __restrict__ out)
{
    const uint32_t smb = smem_u32(dyn_smem);
    const int tid = threadIdx.x, wid = tid >> 5, lane = tid & 31;
    const int m0 = blockIdx.y * 128, n0 = blockIdx.x * 256;

    float acc[4][8][4];
    #pragma unroll
    for (int mt = 0; mt < 4; mt++)
        #pragma unroll
        for (int nt = 0; nt < 8; nt++)
            #pragma unroll
            for (int r = 0; r < 4; r++) acc[mt][nt][r] = 0.0f;

    gemm_core(smb, tid, wid, lane, (size_t)m0 * CQD, (size_t)n0 * CQD,
              CQD, AOs, Wot, acc);

    const int warp_m = wid >> 2, warp_n = wid & 3;
    #pragma unroll
    for (int mt = 0; mt < 4; mt++) {
        int row = m0 + warp_m * 64 + mt * 16 + (lane >> 2);
        #pragma unroll
        for (int nt = 0; nt < 8; nt++) {
            int col = n0 + warp_n * 64 + nt * 8 + (lane & 3) * 2;
            *(float2*)&out[(size_t)row * CHID + col] =
                make_float2(acc[mt][nt][0], acc[mt][nt][1]);
            *(float2*)&out[(size_t)(row + 8) * CHID + col] =
                make_float2(acc[mt][nt][2], acc[mt][nt][3]);
        }
    }
}

// ---------------------------------------------------------------------------
// Fused RMSNorm + neox RoPE -> fp16. Q pre-scaled by QSCALE (exp2 domain).
// ---------------------------------------------------------------------------
__global__ __launch_bounds__(128) void norm_rope_kernel(
    const float* __restrict__ Qm, const float* __restrict__ Km,
    const int* __restrict__ pos,
    const float* __restrict__ qw, const float* __restrict__ kw,
    __half* __restrict__ Qs, __half* __restrict__ Ks)
{
    int t  = blockIdx.x;
    int hh = blockIdx.y;
    const float* base;
    const float* w;
    bool isQ = hh < CH;
    if (isQ) { base = Qm + (size_t)t * CQD + hh * CD;        w = qw; }
    else     { base = Km + (size_t)t * CKD + (hh - CH) * CD; w = kw; }

    int d = threadIdx.x;
    float x1 = base[d];
    float x2 = base[d + 128];
    float ss = x1 * x1 + x2 * x2;
    #pragma unroll
    for (int off = 16; off > 0; off >>= 1)
        ss += __shfl_xor_sync(0xffffffffu, ss, off);
    __shared__ float wsum[4];
    if ((d & 31) == 0) wsum[d >> 5] = ss;
    __syncthreads();
    float tot = wsum[0] + wsum[1] + wsum[2] + wsum[3];
    float inv = rsqrtf(tot * (1.0f / 256.0f) + 1e-6f);
    float n1 = x1 * inv * (1.0f + w[d]);
    float n2 = x2 * inv * (1.0f + w[d + 128]);

    float f = (float)pos[t] * g_invf[d];
    float c, s;
    sincosf(f, &s, &c);
    float o1 = n1 * c - n2 * s;
    float o2 = n2 * c + n1 * s;

    if (isQ) {
        size_t o = (size_t)t * CQD + hh * CD + d;
        Qs[o]       = __float2half_rn(o1 * QSCALE);
        Qs[o + 128] = __float2half_rn(o2 * QSCALE);
    } else {
        size_t o = (size_t)t * CKD + (hh - CH) * CD + d;
        Ks[o]       = __float2half_rn(o1);
        Ks[o + 128] = __float2half_rn(o2);
    }
}

// ---------------------------------------------------------------------------
// FA2-style HMMA flash attention, GQA head pairing + DOUBLE-BUFFERED K/V.
// (unchanged from R13)
// ---------------------------------------------------------------------------
#define FS_Q   0                 // 128 rows x 512 B = 64 KB
#define FS_KV0 65536             // K at +0 (32 KB), V at +32768 (32 KB)
#define FS_KV1 131072
#define FLASH_SMEM 196608        // 192 KB

__device__ __forceinline__ void flash_load_q(
    uint32_t dst, const __half* __restrict__ Qs, int q0, int kvh, int tid)
{
    #pragma unroll
    for (int it = 0; it < 8; it++) {
        int id  = tid + it * 512;
        int row = id >> 5;          // 0..127
        int c16 = id & 31;
        uint32_t sw = (uint32_t)(row * 512) + ((uint32_t)(c16 ^ (row & 7)) << 4);
        int head = row >> 6;
        int r    = row & 63;
        cp_async16(dst + sw, Qs + (size_t)(q0 + r) * CQD +
                                 (kvh * 2 + head) * CD + c16 * 8);
    }
    CP_COMMIT();
}

__device__ __forceinline__ void flash_load_kv(
    uint32_t buf, const __half* __restrict__ Ks, const __half* __restrict__ Vs,
    int t0, int colbase, int tid)
{
    #pragma unroll
    for (int it = 0; it < 4; it++) {
        int id  = tid + it * 512;
        int row = id >> 5;          // 0..63
        int c16 = id & 31;
        uint32_t sw = (uint32_t)(row * 512) + ((uint32_t)(c16 ^ (row & 7)) << 4);
        size_t go = (size_t)(t0 + row) * CKD + colbase + c16 * 8;
        cp_async16(buf + sw,         Ks + go);
        cp_async16(buf + 32768 + sw, Vs + go);
    }
    CP_COMMIT();
}

__global__ __launch_bounds__(512, 1) void flash_hmma_kernel(
    const __half* __restrict__ Qs, const __half* __restrict__ Ks,
    const __half* __restrict__ Vs, __half* __restrict__ AO)
{
    const uint32_t smb = smem_u32(dyn_smem);
    const int tid  = threadIdx.x;
    const int wid  = tid >> 5;
    const int lane = tid & 31;
    const int hh   = wid >> 3;          // head within pair
    const int wq   = (wid >> 1) & 3;    // q-row group
    const int wd   = wid & 1;           // d half
    const int q0   = blockIdx.x * 64;
    const int kvh  = blockIdx.y;
    const int h    = kvh * 2 + hh;

    const int row_in = lane & 15;
    const int hi     = lane >> 4;
    const uint32_t swkey = (uint32_t)(row_in & 7);
    const int qr = lane >> 2;
    const int qc = (lane & 3) * 2;

    float oacc[16][4];
    #pragma unroll
    for (int nt = 0; nt < 16; nt++)
        #pragma unroll
        for (int r = 0; r < 4; r++) oacc[nt][r] = 0.0f;
    float mrun0 = -1e30f, mrun1 = -1e30f, lrun0 = 0.0f, lrun1 = 0.0f;

    int kb_lo = q0 - CWIN;
    if (kb_lo < 0) kb_lo = 0;

    flash_load_q(smb + FS_Q, Qs, q0, kvh, tid);
    flash_load_kv(smb + FS_KV0, Ks, Vs, kb_lo, kvh * CD, tid);

    const uint32_t qbase = smb + FS_Q +
        (uint32_t)(hh * 64 + wq * 16 + row_in) * 512;

    int bufsel = 0;
    for (int k0 = kb_lo; k0 <= q0; k0 += 64, bufsel ^= 1) {
        CP_WAIT(0);
        __syncthreads();

        if (k0 + 64 <= q0)
            flash_load_kv(smb + (bufsel ? FS_KV0 : FS_KV1), Ks, Vs,
                          k0 + 64, kvh * CD, tid);

        const uint32_t kvb = smb + (bufsel ? FS_KV1 : FS_KV0);

        float sacc[8][4];
        #pragma unroll
        for (int nt = 0; nt < 8; nt++)
            #pragma unroll
            for (int r = 0; r < 4; r++) sacc[nt][r] = 0.0f;

        #pragma unroll
        for (int ks = 0; ks < 16; ks++) {
            const uint32_t csw = ((uint32_t)(ks * 2 + hi) ^ swkey) << 4;
            uint32_t aQ[4];
            LDSM_X4(aQ[0], aQ[1], aQ[2], aQ[3], qbase + csw);
            #pragma unroll
            for (int p = 0; p < 4; p++) {
                uint32_t r0, r1, r2, r3;
                LDSM_X4(r0, r1, r2, r3,
                        kvb + (uint32_t)(p * 16 + row_in) * 512 + csw);
                uint32_t b0[2] = {r0, r2}, b1[2] = {r1, r3};
                mma16816(sacc[2 * p],     aQ, b0);
                mma16816(sacc[2 * p + 1], aQ, b1);
            }
        }

        const bool needmask = (k0 + 64 > q0) || (k0 + (CWIN - 64) < q0);
        const int rbase = q0 + wq * 16 + qr;
        if (needmask) {
            #pragma unroll
            for (int nt = 0; nt < 8; nt++) {
                int kg = k0 + nt * 8 + qc;
                #pragma unroll
                for (int e = 0; e < 4; e++) {
                    int qg = rbase + (e >> 1) * 8;
                    int kk = kg + (e & 1);
                    unsigned dd = (unsigned)(qg - kk);
                    if (dd >= (unsigned)CWIN) sacc[nt][e] = -1e30f;
                }
            }
        }

        float mx0 = -1e30f, mx1 = -1e30f;
        #pragma unroll
        for (int nt = 0; nt < 8; nt++) {
            mx0 = fmaxf(mx0, fmaxf(sacc[nt][0], sacc[nt][1]));
            mx1 = fmaxf(mx1, fmaxf(sacc[nt][2], sacc[nt][3]));
        }
        mx0 = fmaxf(mx0, __shfl_xor_sync(0xffffffffu, mx0, 1));
        mx0 = fmaxf(mx0, __shfl_xor_sync(0xffffffffu, mx0, 2));
        mx1 = fmaxf(mx1, __shfl_xor_sync(0xffffffffu, mx1, 1));
        mx1 = fmaxf(mx1, __shfl_xor_sync(0xffffffffu, mx1, 2));

        float newm0 = fmaxf(fmaxf(mrun0, mx0), -1e29f);
        float newm1 = fmaxf(fmaxf(mrun1, mx1), -1e29f);
        float alpha0 = fast_exp2(mrun0 - newm0);
        float alpha1 = fast_exp2(mrun1 - newm1);
        mrun0 = newm0; mrun1 = newm1;

        float rs0 = 0.0f, rs1 = 0.0f;
        #pragma unroll
        for (int nt = 0; nt < 8; nt++) {
            sacc[nt][0] = fast_exp2(sacc[nt][0] - newm0);
            sacc[nt][1] = fast_exp2(sacc[nt][1] - newm0);
            sacc[nt][2] = fast_exp2(sacc[nt][2] - newm1);
            sacc[nt][3] = fast_exp2(sacc[nt][3] - newm1);
            rs0 += sacc[nt][0] + sacc[nt][1];
            rs1 += sacc[nt][2] + sacc[nt][3];
        }
        rs0 += __shfl_xor_sync(0xffffffffu, rs0, 1);
        rs0 += __shfl_xor_sync(0xffffffffu, rs0, 2);
        rs1 += __shfl_xor_sync(0xffffffffu, rs1, 1);
        rs1 += __shfl_xor_sync(0xffffffffu, rs1, 2);
        lrun0 = lrun0 * alpha0 + rs0;
        lrun1 = lrun1 * alpha1 + rs1;

        uint32_t pa[4][4];
        #pragma unroll
        for (int c = 0; c < 4; c++) {
            pa[c][0] = packh2(sacc[2 * c][0],     sacc[2 * c][1]);
            pa[c][1] = packh2(sacc[2 * c][2],     sacc[2 * c][3]);
            pa[c][2] = packh2(sacc[2 * c + 1][0], sacc[2 * c + 1][1]);
            pa[c][3] = packh2(sacc[2 * c + 1][2], sacc[2 * c + 1][3]);
        }

        #pragma unroll
        for (int nt = 0; nt < 16; nt++) {
            oacc[nt][0] *= alpha0; oacc[nt][1] *= alpha0;
            oacc[nt][2] *= alpha1; oacc[nt][3] *= alpha1;
        }
        const uint32_t vbase = kvb + 32768;
        #pragma unroll
        for (int c = 0; c < 4; c++) {
            #pragma unroll
            for (int j = 0; j < 8; j++) {
                uint32_t c16v = (uint32_t)(wd * 16 + j * 2 + hi);
                uint32_t offV = (uint32_t)(c * 16 + row_in) * 512 +
                                ((c16v ^ swkey) << 4);
                uint32_t h0, h1, h2, h3;
                LDSM_X4_T(h0, h1, h2, h3, vbase + offV);
                uint32_t b0[2] = {h0, h1}, b1[2] = {h2, h3};
                mma16816(oacc[2 * j],     pa[c], b0);
                mma16816(oacc[2 * j + 1], pa[c], b1);
            }
        }
    }

    float inv0 = 1.0f / lrun0, inv1 = 1.0f / lrun1;
    int row0 = q0 + wq * 16 + qr;
    #pragma unroll
    for (int nt = 0; nt < 16; nt++) {
        int col = h * CD + wd * 128 + nt * 8 + qc;
        *(__half2*)&AO[(size_t)row0 * CQD + col] =
            __floats2half2_rn(oacc[nt][0] * inv0, oacc[nt][1] * inv0);
        *(__half2*)&AO[(size_t)(row0 + 8) * CQD + col] =
            __floats2half2_rn(oacc[nt][2] * inv1, oacc[nt][3] * inv1);
    }
}

// ---------------------------------------------------------------------------
extern "C" void kernel_launch(void* const* d_in, const int* in_sizes, int n_in,
                              void* d_out, int out_size) {
    const float* x  = (const float*)d_in[0];
    const int*   ps = (const int*)  d_in[1];
    const float* Wq = (const float*)d_in[2];
    const float* Wk = (const float*)d_in[3];
    const float* Wv = (const float*)d_in[4];
    const float* Wo = (const float*)d_in[5];
    const float* qw = (const float*)d_in[6];
    const float* kw = (const float*)d_in[7];
    float* out = (float*)d_out;
    (void)in_sizes; (void)n_in; (void)out_size;

    float *Qp, *Kp;
    cudaGetSymbolAddress((void**)&Qp, g_Q);
    cudaGetSymbolAddress((void**)&Kp, g_K);
    __half *xs, *Wqkv, *Wot, *Qss, *Kss, *Vss, *AOs;
    cudaGetSymbolAddress((void**)&xs,   g_xs);
    cudaGetSymbolAddress((void**)&Wqkv, g_Wqkv);
    cudaGetSymbolAddress((void**)&Wot,  g_Wot);
    cudaGetSymbolAddress((void**)&Qss,  g_Qs);
    cudaGetSymbolAddress((void**)&Kss,  g_Ks);
    cudaGetSymbolAddress((void**)&Vss,  g_Vs);
    cudaGetSymbolAddress((void**)&AOs,  g_AOs);

    cudaFuncSetAttribute(gemm_qkv_kernel,
                         cudaFuncAttributeMaxDynamicSharedMemorySize, GEMM_SMEM);
    cudaFuncSetAttribute(gemm_o_kernel,
                         cudaFuncAttributeMaxDynamicSharedMemorySize, GEMM_SMEM);
    cudaFuncSetAttribute(flash_hmma_kernel,
                         cudaFuncAttributeMaxDynamicSharedMemorySize, FLASH_SMEM);

    // launch order: ncu (-s 5 -c 1) captures launch #6 = flash
    init_invf_kernel<<<1, 128>>>();                                      // 1
    convert_f16_kernel<<<512, 256>>>(x, xs, CT * CHID);                  // 2
    transpose_all_kernel<<<dim3(80, 80, 4), 256>>>(                      // 3
        Wq, Wk, Wv, Wo, Wqkv, Wot);

    gemm_qkv_kernel<<<dim3((CQD + 2 * CKD) / 256, CT / 128), 256,        // 4
                      GEMM_SMEM>>>(xs, Wqkv, Qp, Kp, Vss);

    norm_rope_kernel<<<dim3(CT, CH + CKH), 128>>>(Qp, Kp, ps, qw, kw,    // 5
                                                  Qss, Kss);

    flash_hmma_kernel<<<dim3(CT / 64, CKH), 512, FLASH_SMEM>>>(          // 6 <- ncu
        Qss, Kss, Vss, AOs);

    gemm_o_kernel<<<dim3(CHID / 256, CT / 128), 256, GEMM_SMEM>>>(       // 7
        AOs, Wot, out);
}

// round 15
// speedup vs baseline: 1.2404x; 1.2404x over previous
#include <cuda_runtime.h>
#include <cuda_fp16.h>
#include <math.h>
#include <stdint.h>

#define CT   4096
#define CHID 2560
#define CH   8
#define CKH  4
#define CD   256
#define CQD  2048   // H*D
#define CKD  1024   // KH*D
#define CWIN 1024
#define LOG2E 1.4426950408889634f
#define QSCALE (0.0625f * LOG2E)

// ---------------- scratch (static device globals) ----------------
__device__ float g_Q[CT * CQD];          // f32 Q proj (pre-norm)
__device__ float g_K[CT * CKD];          // f32 K proj (pre-norm)
__device__ float g_invf[128];

__device__ __half g_xs[CT * CHID];                  // x fp16
__device__ __half g_Wqkv[(CQD + 2 * CKD) * CHID];   // [4096, 2560] concat [N,K]
__device__ __half g_Wot[CHID * CQD];                // Wo^T [2560, 2048]

__device__ __half g_Qs[CT * CQD];        // flash operands fp16
__device__ __half g_Ks[CT * CKD];
__device__ __half g_Vs[CT * CKD];
__device__ __half g_AOs[CT * CQD];       // attention output fp16

extern __shared__ char dyn_smem[];

// ---------------- PTX helpers (compute_103-safe) ----------------
__device__ __forceinline__ uint32_t smem_u32(const void* p) {
    uint32_t a;
    asm("{ .reg .u64 t; cvta.to.shared.u64 t, %1; cvt.u32.u64 %0, t; }"
        : "=r"(a) : "l"(p));
    return a;
}
__device__ __forceinline__ void cp_async16(uint32_t s, const void* g) {
    asm volatile("cp.async.cg.shared.global [%0], [%1], 16;" :: "r"(s), "l"(g));
}
#define CP_COMMIT()  asm volatile("cp.async.commit_group;" ::: "memory")
#define CP_WAIT(n)   asm volatile("cp.async.wait_group %0;" :: "n"(n) : "memory")

#define LDSM_X4(r0, r1, r2, r3, addr) \
    asm volatile("ldmatrix.sync.aligned.m8n8.x4.shared.b16 {%0,%1,%2,%3}, [%4];" \
                 : "=r"(r0), "=r"(r1), "=r"(r2), "=r"(r3) : "r"(addr))
#define LDSM_X4_T(r0, r1, r2, r3, addr) \
    asm volatile("ldmatrix.sync.aligned.m8n8.x4.trans.shared.b16 {%0,%1,%2,%3}, [%4];" \
                 : "=r"(r0), "=r"(r1), "=r"(r2), "=r"(r3) : "r"(addr))

__device__ __forceinline__ void mma16816(float* d, const uint32_t* a,
                                         const uint32_t* b) {
    asm volatile(
        "mma.sync.aligned.m16n8k16.row.col.f32.f16.f16.f32 "
        "{%0,%1,%2,%3}, {%4,%5,%6,%7}, {%8,%9}, {%0,%1,%2,%3};"
        : "+f"(d[0]), "+f"(d[1]), "+f"(d[2]), "+f"(d[3])
        : "r"(a[0]), "r"(a[1]), "r"(a[2]), "r"(a[3]), "r"(b[0]), "r"(b[1]));
}
__device__ __forceinline__ float fast_exp2(float x) {
    float y;
    asm("ex2.approx.ftz.f32 %0, %1;" : "=f"(y) : "f"(x));
    return y;
}
__device__ __forceinline__ uint32_t packh2(float a, float b) {
    __half2 t = __floats2half2_rn(a, b);
    return *(uint32_t*)&t;
}

// ---------------- small prep kernels ----------------
__global__ void init_invf_kernel() {
    int d = threadIdx.x;
    if (d < 128) g_invf[d] = (float)pow(10000.0, -((double)d) / 128.0);
}

__global__ __launch_bounds__(256) void convert_f16_kernel(
    const float* __restrict__ x, __half* __restrict__ y, int n)
{
    int i = blockIdx.x * 256 + threadIdx.x;
    int stride = gridDim.x * 256;
    for (; i < n; i += stride) y[i] = __float2half_rn(x[i]);
}

// All weight transposes in ONE launch (z selects matrix). W[K,N] -> T[N,K] fp16.
__global__ __launch_bounds__(256) void transpose_all_kernel(
    const float* __restrict__ Wq, const float* __restrict__ Wk,
    const float* __restrict__ Wv, const float* __restrict__ Wo,
    __half* __restrict__ Wqkv, __half* __restrict__ Wot)
{
    const float* W;
    __half* Th;
    int K, N;
    switch (blockIdx.z) {
        case 0: W = Wq; Th = Wqkv;                              K = CHID; N = CQD; break;
        case 1: W = Wk; Th = Wqkv + (size_t)CQD * CHID;         K = CHID; N = CKD; break;
        case 2: W = Wv; Th = Wqkv + (size_t)(CQD + CKD) * CHID; K = CHID; N = CKD; break;
        default: W = Wo; Th = Wot;                              K = CQD;  N = CHID; break;
    }
    int n0 = blockIdx.x * 32, k0 = blockIdx.y * 32;
    if (n0 >= N || k0 >= K) return;

    __shared__ float t[32][33];
    int tx = threadIdx.x & 31, ty = threadIdx.x >> 5;
    #pragma unroll
    for (int r = 0; r < 4; r++)
        t[ty + 8 * r][tx] = W[(size_t)(k0 + ty + 8 * r) * N + n0 + tx];
    __syncthreads();
    #pragma unroll
    for (int r = 0; r < 4; r++)
        Th[(size_t)(n0 + ty + 8 * r) * K + k0 + tx] =
            __float2half_rn(t[tx][ty + 8 * r]);
}

// ---------------------------------------------------------------------------
// HMMA fp16 GEMM core (R13 config): 128x128 CTA tile, 8 warps (64x32 warp
// tile), BK=64, 3-stage cp.async, ONE syncthreads per chunk, 2 CTA/SM.
// ---------------------------------------------------------------------------
#define GSTG 32768
#define GEMM_SMEM (3 * GSTG)

__device__ __forceinline__ void gemm_issue(
    uint32_t st, int tid, size_t aBase, size_t bBase, int k0, int K,
    const __half* __restrict__ A, const __half* __restrict__ B)
{
    #pragma unroll
    for (int it = 0; it < 4; it++) {
        int id  = tid + it * 256;
        int row = id >> 3;
        int c16 = id & 7;
        uint32_t sw = (uint32_t)(row * 128) + ((uint32_t)(c16 ^ (row & 7)) << 4);
        size_t go = (size_t)row * K + k0 + c16 * 8;
        cp_async16(st + sw,         A + aBase + go);
        cp_async16(st + 16384 + sw, B + bBase + go);
    }
    CP_COMMIT();
}

__device__ __forceinline__ void gemm_core(
    uint32_t smb, int tid, int wid, int lane,
    size_t aBase, size_t bBase, int K,
    const __half* __restrict__ A, const __half* __restrict__ B,
    float acc[4][4][4])
{
    const int warp_m = wid >> 2;
    const int warp_n = wid & 3;
    const int NC = K >> 6;
    const int row_in = lane & 15;
    const int hi     = lane >> 4;
    const uint32_t swkey = (uint32_t)(row_in & 7);

    gemm_issue(smb, tid, aBase, bBase, 0, K, A, B);
    if (NC > 1) gemm_issue(smb + GSTG, tid, aBase, bBase, 64, K, A, B);

    for (int c = 0; c < NC; c++) {
        CP_WAIT(1);
        __syncthreads();
        if (c + 2 < NC)
            gemm_issue(smb + ((c + 2) % 3) * GSTG, tid, aBase, bBase,
                       (c + 2) << 6, K, A, B);
        const uint32_t sA = smb + (c % 3) * GSTG;
        const uint32_t sB = sA + 16384;

        #pragma unroll
        for (int ks = 0; ks < 4; ks++) {
            const uint32_t csw = ((uint32_t)(ks * 2 + hi) ^ swkey) << 4;
            uint32_t ah[4][4];
            #pragma unroll
            for (int mt = 0; mt < 4; mt++) {
                uint32_t off = (uint32_t)(warp_m * 64 + mt * 16 + row_in) * 128 + csw;
                LDSM_X4(ah[mt][0], ah[mt][1], ah[mt][2], ah[mt][3], sA + off);
            }
            uint32_t bf[4][2];
            #pragma unroll
            for (int p = 0; p < 2; p++) {
                uint32_t off = (uint32_t)(warp_n * 32 + p * 16 + row_in) * 128 + csw;
                uint32_t r0, r1, r2, r3;
                LDSM_X4(r0, r1, r2, r3, sB + off);
                bf[2 * p][0] = r0; bf[2 * p + 1][0] = r1;
                bf[2 * p][1] = r2; bf[2 * p + 1][1] = r3;
            }
            #pragma unroll
            for (int mt = 0; mt < 4; mt++)
                #pragma unroll
                for (int nt = 0; nt < 4; nt++)
                    mma16816(acc[mt][nt], ah[mt], bf[nt]);
        }
    }
}

// Fused QKV projection: N = 4096 concat (Q 2048 f32 | K 1024 f32 | V 1024 fp16)
__global__ __launch_bounds__(256, 2) void gemm_qkv_kernel(
    const __half* __restrict__ xs, const __half* __restrict__ Wqkv,
    float* __restrict__ Qf, float* __restrict__ Kf, __half* __restrict__ Vh)
{
    const uint32_t smb = smem_u32(dyn_smem);
    const int tid = threadIdx.x, wid = tid >> 5, lane = tid & 31;
    const int m0 = blockIdx.y * 128, n0 = blockIdx.x * 128;

    float acc[4][4][4];
    #pragma unroll
    for (int mt = 0; mt < 4; mt++)
        #pragma unroll
        for (int nt = 0; nt < 4; nt++)
            #pragma unroll
            for (int r = 0; r < 4; r++) acc[mt][nt][r] = 0.0f;

    gemm_core(smb, tid, wid, lane, (size_t)m0 * CHID, (size_t)n0 * CHID,
              CHID, xs, Wqkv, acc);

    float* Cf = nullptr; __half* Chh = nullptr;
    int ld, cb;
    if (n0 < CQD)            { Cf = Qf; ld = CQD; cb = n0; }
    else if (n0 < CQD + CKD) { Cf = Kf; ld = CKD; cb = n0 - CQD; }
    else                     { Chh = Vh; ld = CKD; cb = n0 - CQD - CKD; }

    const int warp_m = wid >> 2, warp_n = wid & 3;
    #pragma unroll
    for (int mt = 0; mt < 4; mt++) {
        int row = m0 + warp_m * 64 + mt * 16 + (lane >> 2);
        #pragma unroll
        for (int nt = 0; nt < 4; nt++) {
            int col = cb + warp_n * 32 + nt * 8 + (lane & 3) * 2;
            if (Chh) {
                *(__half2*)&Chh[(size_t)row * ld + col] =
                    __floats2half2_rn(acc[mt][nt][0], acc[mt][nt][1]);
                *(__half2*)&Chh[(size_t)(row + 8) * ld + col] =
                    __floats2half2_rn(acc[mt][nt][2], acc[mt][nt][3]);
            } else {
                *(float2*)&Cf[(size_t)row * ld + col] =
                    make_float2(acc[mt][nt][0], acc[mt][nt][1]);
                *(float2*)&Cf[(size_t)(row + 8) * ld + col] =
                    make_float2(acc[mt][nt][2], acc[mt][nt][3]);
            }
        }
    }
}

// Output projection: out[T, HID] = AO[T, QD] @ Wot[HID, QD]^T, f32 out
__global__ __launch_bounds__(256, 2) void gemm_o_kernel(
    const __half* __restrict__ AOs, const __half* __restrict__ Wot,
    float* __restrict__ out)
{
    const uint32_t smb = smem_u32(dyn_smem);
    const int tid = threadIdx.x, wid = tid >> 5, lane = tid & 31;
    const int m0 = blockIdx.y * 128, n0 = blockIdx.x * 128;

    float acc[4][4][4];
    #pragma unroll
    for (int mt = 0; mt < 4; mt++)
        #pragma unroll
        for (int nt = 0; nt < 4; nt++)
            #pragma unroll
            for (int r = 0; r < 4; r++) acc[mt][nt][r] = 0.0f;

    gemm_core(smb, tid, wid, lane, (size_t)m0 * CQD, (size_t)n0 * CQD,
              CQD, AOs, Wot, acc);

    const int warp_m = wid >> 2, warp_n = wid & 3;
    #pragma unroll
    for (int mt = 0; mt < 4; mt++) {
        int row = m0 + warp_m * 64 + mt * 16 + (lane >> 2);
        #pragma unroll
        for (int nt = 0; nt < 4; nt++) {
            int col = n0 + warp_n * 32 + nt * 8 + (lane & 3) * 2;
            *(float2*)&out[(size_t)row * CHID + col] =
                make_float2(acc[mt][nt][0], acc[mt][nt][1]);
            *(float2*)&out[(size_t)(row + 8) * CHID + col] =
                make_float2(acc[mt][nt][2], acc[mt][nt][3]);
        }
    }
}

// ---------------------------------------------------------------------------
// Fused RMSNorm + neox RoPE -> fp16. Q pre-scaled by QSCALE (exp2 domain).
// ---------------------------------------------------------------------------
__global__ __launch_bounds__(128) void norm_rope_kernel(
    const float* __restrict__ Qm, const float* __restrict__ Km,
    const int* __restrict__ pos,
    const float* __restrict__ qw, const float* __restrict__ kw,
    __half* __restrict__ Qs, __half* __restrict__ Ks)
{
    int t  = blockIdx.x;
    int hh = blockIdx.y;
    const float* base;
    const float* w;
    bool isQ = hh < CH;
    if (isQ) { base = Qm + (size_t)t * CQD + hh * CD;        w = qw; }
    else     { base = Km + (size_t)t * CKD + (hh - CH) * CD; w = kw; }

    int d = threadIdx.x;
    float x1 = base[d];
    float x2 = base[d + 128];
    float ss = x1 * x1 + x2 * x2;
    #pragma unroll
    for (int off = 16; off > 0; off >>= 1)
        ss += __shfl_xor_sync(0xffffffffu, ss, off);
    __shared__ float wsum[4];
    if ((d & 31) == 0) wsum[d >> 5] = ss;
    __syncthreads();
    float tot = wsum[0] + wsum[1] + wsum[2] + wsum[3];
    float inv = rsqrtf(tot * (1.0f / 256.0f) + 1e-6f);
    float n1 = x1 * inv * (1.0f + w[d]);
    float n2 = x2 * inv * (1.0f + w[d + 128]);

    float f = (float)pos[t] * g_invf[d];
    float c, s;
    sincosf(f, &s, &c);
    float o1 = n1 * c - n2 * s;
    float o2 = n2 * c + n1 * s;

    if (isQ) {
        size_t o = (size_t)t * CQD + hh * CD + d;
        Qs[o]       = __float2half_rn(o1 * QSCALE);
        Qs[o + 128] = __float2half_rn(o2 * QSCALE);
    } else {
        size_t o = (size_t)t * CKD + (hh - CH) * CD + d;
        Ks[o]       = __float2half_rn(o1);
        Ks[o + 128] = __float2half_rn(o2);
    }
}

// ---------------------------------------------------------------------------
// FA2-style HMMA flash attention v3: NO QK duplication.
// CTA: 64 q rows x 2 heads (128 logical rows), 256 thr = 8 warps.
// Warp (hh = wid>>2, wq = wid&3) owns 16 q rows; computes full 64 kv QK,
// warp-local softmax (once per row), and FULL 256-d PV (oacc 32 n8-tiles).
// Double-buffered K/V, one syncthreads per tile.
// ---------------------------------------------------------------------------
#define FS_Q   0                 // 128 rows x 512 B = 64 KB
#define FS_KV0 65536             // K at +0 (32 KB), V at +32768 (32 KB)
#define FS_KV1 131072
#define FLASH_SMEM 196608        // 192 KB

__device__ __forceinline__ void flash_load_q(
    uint32_t dst, const __half* __restrict__ Qs, int q0, int kvh, int tid)
{
    #pragma unroll
    for (int it = 0; it < 16; it++) {
        int id  = tid + it * 256;
        int row = id >> 5;          // 0..127
        int c16 = id & 31;
        uint32_t sw = (uint32_t)(row * 512) + ((uint32_t)(c16 ^ (row & 7)) << 4);
        int head = row >> 6;
        int r    = row & 63;
        cp_async16(dst + sw, Qs + (size_t)(q0 + r) * CQD +
                                 (kvh * 2 + head) * CD + c16 * 8);
    }
    CP_COMMIT();
}

__device__ __forceinline__ void flash_load_kv(
    uint32_t buf, const __half* __restrict__ Ks, const __half* __restrict__ Vs,
    int t0, int colbase, int tid)
{
    #pragma unroll
    for (int it = 0; it < 8; it++) {
        int id  = tid + it * 256;
        int row = id >> 5;          // 0..63
        int c16 = id & 31;
        uint32_t sw = (uint32_t)(row * 512) + ((uint32_t)(c16 ^ (row & 7)) << 4);
        size_t go = (size_t)(t0 + row) * CKD + colbase + c16 * 8;
        cp_async16(buf + sw,         Ks + go);
        cp_async16(buf + 32768 + sw, Vs + go);
    }
    CP_COMMIT();
}

__global__ __launch_bounds__(256, 1) void flash_hmma_kernel(
    const __half* __restrict__ Qs, const __half* __restrict__ Ks,
    const __half* __restrict__ Vs, __half* __restrict__ AO)
{
    const uint32_t smb = smem_u32(dyn_smem);
    const int tid  = threadIdx.x;
    const int wid  = tid >> 5;
    const int lane = tid & 31;
    const int hh   = wid >> 2;          // head within pair
    const int wq   = wid & 3;           // q-row group
    const int q0   = blockIdx.x * 64;
    const int kvh  = blockIdx.y;
    const int h    = kvh * 2 + hh;

    const int row_in = lane & 15;
    const int hi     = lane >> 4;
    const uint32_t swkey = (uint32_t)(row_in & 7);
    const int qr = lane >> 2;
    const int qc = (lane & 3) * 2;

    // 16 q rows x 256 d = 32 n8 accumulator tiles
    float oacc[32][4];
    #pragma unroll
    for (int nt = 0; nt < 32; nt++)
        #pragma unroll
        for (int r = 0; r < 4; r++) oacc[nt][r] = 0.0f;
    float mrun0 = -1e30f, mrun1 = -1e30f, lrun0 = 0.0f, lrun1 = 0.0f;

    int kb_lo = q0 - CWIN;
    if (kb_lo < 0) kb_lo = 0;

    flash_load_q(smb + FS_Q, Qs, q0, kvh, tid);
    flash_load_kv(smb + FS_KV0, Ks, Vs, kb_lo, kvh * CD, tid);

    const uint32_t qbase = smb + FS_Q +
        (uint32_t)(hh * 64 + wq * 16 + row_in) * 512;

    int bufsel = 0;
    for (int k0 = kb_lo; k0 <= q0; k0 += 64, bufsel ^= 1) {
        CP_WAIT(0);
        __syncthreads();

        if (k0 + 64 <= q0)
            flash_load_kv(smb + (bufsel ? FS_KV0 : FS_KV1), Ks, Vs,
                          k0 + 64, kvh * CD, tid);

        const uint32_t kvb = smb + (bufsel ? FS_KV1 : FS_KV0);

        // ---- S = Q K^T over all 64 kv ----
        float sacc[8][4];
        #pragma unroll
        for (int nt = 0; nt < 8; nt++)
            #pragma unroll
            for (int r = 0; r < 4; r++) sacc[nt][r] = 0.0f;

        #pragma unroll
        for (int ks = 0; ks < 16; ks++) {
            const uint32_t csw = ((uint32_t)(ks * 2 + hi) ^ swkey) << 4;
            uint32_t aQ[4];
            LDSM_X4(aQ[0], aQ[1], aQ[2], aQ[3], qbase + csw);
            #pragma unroll
            for (int p = 0; p < 4; p++) {
                uint32_t r0, r1, r2, r3;
                LDSM_X4(r0, r1, r2, r3,
                        kvb + (uint32_t)(p * 16 + row_in) * 512 + csw);
                uint32_t b0[2] = {r0, r2}, b1[2] = {r1, r3};
                mma16816(sacc[2 * p],     aQ, b0);
                mma16816(sacc[2 * p + 1], aQ, b1);
            }
        }

        // ---- mask (edge tiles only) ----
        const bool needmask = (k0 + 64 > q0) || (k0 + (CWIN - 64) < q0);
        const int rbase = q0 + wq * 16 + qr;
        if (needmask) {
            #pragma unroll
            for (int nt = 0; nt < 8; nt++) {
                int kg = k0 + nt * 8 + qc;
                #pragma unroll
                for (int e = 0; e < 4; e++) {
                    int qg = rbase + (e >> 1) * 8;
                    int kk = kg + (e & 1);
                    unsigned dd = (unsigned)(qg - kk);
                    if (dd >= (unsigned)CWIN) sacc[nt][e] = -1e30f;
                }
            }
        }

        // ---- warp-local online softmax (once per q row) ----
        float mx0 = -1e30f, mx1 = -1e30f;
        #pragma unroll
        for (int nt = 0; nt < 8; nt++) {
            mx0 = fmaxf(mx0, fmaxf(sacc[nt][0], sacc[nt][1]));
            mx1 = fmaxf(mx1, fmaxf(sacc[nt][2], sacc[nt][3]));
        }
        mx0 = fmaxf(mx0, __shfl_xor_sync(0xffffffffu, mx0, 1));
        mx0 = fmaxf(mx0, __shfl_xor_sync(0xffffffffu, mx0, 2));
        mx1 = fmaxf(mx1, __shfl_xor_sync(0xffffffffu, mx1, 1));
        mx1 = fmaxf(mx1, __shfl_xor_sync(0xffffffffu, mx1, 2));

        float newm0 = fmaxf(fmaxf(mrun0, mx0), -1e29f);
        float newm1 = fmaxf(fmaxf(mrun1, mx1), -1e29f);
        float alpha0 = fast_exp2(mrun0 - newm0);
        float alpha1 = fast_exp2(mrun1 - newm1);
        mrun0 = newm0; mrun1 = newm1;

        float rs0 = 0.0f, rs1 = 0.0f;
        #pragma unroll
        for (int nt = 0; nt < 8; nt++) {
            sacc[nt][0] = fast_exp2(sacc[nt][0] - newm0);
            sacc[nt][1] = fast_exp2(sacc[nt][1] - newm0);
            sacc[nt][2] = fast_exp2(sacc[nt][2] - newm1);
            sacc[nt][3] = fast_exp2(sacc[nt][3] - newm1);
            rs0 += sacc[nt][0] + sacc[nt][1];
            rs1 += sacc[nt][2] + sacc[nt][3];
        }
        rs0 += __shfl_xor_sync(0xffffffffu, rs0, 1);
        rs0 += __shfl_xor_sync(0xffffffffu, rs0, 2);
        rs1 += __shfl_xor_sync(0xffffffffu, rs1, 1);
        rs1 += __shfl_xor_sync(0xffffffffu, rs1, 2);
        lrun0 = lrun0 * alpha0 + rs0;
        lrun1 = lrun1 * alpha1 + rs1;

        // ---- P acc fragments -> A fragments, in registers ----
        uint32_t pa[4][4];
        #pragma unroll
        for (int c = 0; c < 4; c++) {
            pa[c][0] = packh2(sacc[2 * c][0],     sacc[2 * c][1]);
            pa[c][1] = packh2(sacc[2 * c][2],     sacc[2 * c][3]);
            pa[c][2] = packh2(sacc[2 * c + 1][0], sacc[2 * c + 1][1]);
            pa[c][3] = packh2(sacc[2 * c + 1][2], sacc[2 * c + 1][3]);
        }

        // ---- rescale O, O += P V over FULL 256 d ----
        #pragma unroll
        for (int nt = 0; nt < 32; nt++) {
            oacc[nt][0] *= alpha0; oacc[nt][1] *= alpha0;
            oacc[nt][2] *= alpha1; oacc[nt][3] *= alpha1;
        }
        const uint32_t vbase = kvb + 32768;
        #pragma unroll
        for (int c = 0; c < 4; c++) {
            #pragma unroll
            for (int j = 0; j < 16; j++) {
                uint32_t c16v = (uint32_t)(j * 2 + hi);
                uint32_t offV = (uint32_t)(c * 16 + row_in) * 512 +
                                ((c16v ^ swkey) << 4);
                uint32_t h0, h1, h2, h3;
                LDSM_X4_T(h0, h1, h2, h3, vbase + offV);
                uint32_t b0[2] = {h0, h1}, b1[2] = {h2, h3};
                mma16816(oacc[2 * j],     pa[c], b0);
                mma16816(oacc[2 * j + 1], pa[c], b1);
            }
        }
    }

    // ---- epilogue: fp16 AO, 16 rows x 256 cols per warp ----
    float inv0 = 1.0f / lrun0, inv1 = 1.0f / lrun1;
    int row0 = q0 + wq * 16 + qr;
    #pragma unroll
    for (int nt = 0; nt < 32; nt++) {
        int col = h * CD + nt * 8 + qc;
        *(__half2*)&AO[(size_t)row0 * CQD + col] =
            __floats2half2_rn(oacc[nt][0] * inv0, oacc[nt][1] * inv0);
        *(__half2*)&AO[(size_t)(row0 + 8) * CQD + col] =
            __floats2half2_rn(oacc[nt][2] * inv1, oacc[nt][3] * inv1);
    }
}

// ---------------------------------------------------------------------------
extern "C" void kernel_launch(void* const* d_in, const int* in_sizes, int n_in,
                              void* d_out, int out_size) {
    const float* x  = (const float*)d_in[0];
    const int*   ps = (const int*)  d_in[1];
    const float* Wq = (const float*)d_in[2];
    const float* Wk = (const float*)d_in[3];
    const float* Wv = (const float*)d_in[4];
    const float* Wo = (const float*)d_in[5];
    const float* qw = (const float*)d_in[6];
    const float* kw = (const float*)d_in[7];
    float* out = (float*)d_out;
    (void)in_sizes; (void)n_in; (void)out_size;

    float *Qp, *Kp;
    cudaGetSymbolAddress((void**)&Qp, g_Q);
    cudaGetSymbolAddress((void**)&Kp, g_K);
    __half *xs, *Wqkv, *Wot, *Qss, *Kss, *Vss, *AOs;
    cudaGetSymbolAddress((void**)&xs,   g_xs);
    cudaGetSymbolAddress((void**)&Wqkv, g_Wqkv);
    cudaGetSymbolAddress((void**)&Wot,  g_Wot);
    cudaGetSymbolAddress((void**)&Qss,  g_Qs);
    cudaGetSymbolAddress((void**)&Kss,  g_Ks);
    cudaGetSymbolAddress((void**)&Vss,  g_Vs);
    cudaGetSymbolAddress((void**)&AOs,  g_AOs);

    cudaFuncSetAttribute(gemm_qkv_kernel,
                         cudaFuncAttributeMaxDynamicSharedMemorySize, GEMM_SMEM);
    cudaFuncSetAttribute(gemm_o_kernel,
                         cudaFuncAttributeMaxDynamicSharedMemorySize, GEMM_SMEM);
    cudaFuncSetAttribute(flash_hmma_kernel,
                         cudaFuncAttributeMaxDynamicSharedMemorySize, FLASH_SMEM);

    // launch order: ncu (-s 5 -c 1) captures launch #6 = flash
    init_invf_kernel<<<1, 128>>>();                                      // 1
    convert_f16_kernel<<<512, 256>>>(x, xs, CT * CHID);                  // 2
    transpose_all_kernel<<<dim3(80, 80, 4), 256>>>(                      // 3
        Wq, Wk, Wv, Wo, Wqkv, Wot);

    gemm_qkv_kernel<<<dim3((CQD + 2 * CKD) / 128, CT / 128), 256,        // 4
                      GEMM_SMEM>>>(xs, Wqkv, Qp, Kp, Vss);

    norm_rope_kernel<<<dim3(CT, CH + CKH), 128>>>(Qp, Kp, ps, qw, kw,    // 5
                                                  Qss, Kss);

    flash_hmma_kernel<<<dim3(CT / 64, CKH), 256, FLASH_SMEM>>>(          // 6 <- ncu
        Qss, Kss, Vss, AOs);

    gemm_o_kernel<<<dim3(CHID / 128, CT / 128), 256, GEMM_SMEM>>>(       // 7
        AOs, Wot, out);
}